// round 1
// baseline (speedup 1.0000x reference)
#include <cuda_runtime.h>
#include <cuda_bf16.h>
#include <cstddef>

#define N_NEWS 100000
#define DIM    128
#define KDIM   384   // 3*DIM
#define HIDN   512
#define OUTD   128

// Scratch (allocation-free rule: __device__ globals)
__device__ float g_ent_sum[(size_t)N_NEWS * DIM];
__device__ float g_top_sum[(size_t)N_NEWS * DIM];
__device__ float g_ent_deg[N_NEWS];
__device__ float g_top_deg[N_NEWS];
__device__ float g_X[(size_t)N_NEWS * KDIM];
__device__ float g_H[(size_t)N_NEWS * HIDN];

// -------------------- edge scatter: one warp per edge --------------------
__global__ void scatter_kernel(const float* __restrict__ feats,
                               const int*  __restrict__ row,
                               const int*  __restrict__ col,
                               float* __restrict__ sum,
                               float* __restrict__ deg,
                               int n_edges) {
    int warp = (blockIdx.x * blockDim.x + threadIdx.x) >> 5;
    int lane = threadIdx.x & 31;
    if (warp >= n_edges) return;
    int r = row[warp];
    int c = col[warp];
    float4 v = reinterpret_cast<const float4*>(feats + (size_t)c * DIM)[lane];
    float* dst = sum + (size_t)r * DIM + lane * 4;
    atomicAdd(dst + 0, v.x);
    atomicAdd(dst + 1, v.y);
    atomicAdd(dst + 2, v.z);
    atomicAdd(dst + 3, v.w);
    if (lane == 0) atomicAdd(deg + r, 1.0f);
}

// -------------------- build X = [news | ent_sum/deg | top_sum/deg] ------
__global__ void build_x_kernel(const float* __restrict__ news) {
    int idx = blockIdx.x * blockDim.x + threadIdx.x;   // float4 index
    const int F4_PER_ROW = KDIM / 4;                   // 96
    if (idx >= N_NEWS * F4_PER_ROW) return;
    int r  = idx / F4_PER_ROW;
    int j4 = idx - r * F4_PER_ROW;
    float4 v;
    if (j4 < 32) {
        v = reinterpret_cast<const float4*>(news)[(size_t)r * 32 + j4];
    } else if (j4 < 64) {
        float inv = 1.0f / (g_ent_deg[r] + 1e-8f);
        float4 s = reinterpret_cast<const float4*>(g_ent_sum)[(size_t)r * 32 + (j4 - 32)];
        v = make_float4(s.x * inv, s.y * inv, s.z * inv, s.w * inv);
    } else {
        float inv = 1.0f / (g_top_deg[r] + 1e-8f);
        float4 s = reinterpret_cast<const float4*>(g_top_sum)[(size_t)r * 32 + (j4 - 64)];
        v = make_float4(s.x * inv, s.y * inv, s.z * inv, s.w * inv);
    }
    reinterpret_cast<float4*>(g_X)[idx] = v;
}

// -------------------- fp32 tiled GEMM + bias (+ optional tanh) ----------
// C[M,N] = act(A[M,K] @ B[K,N] + bias[N]).  BM=BN=64, BK=16, 256 thr, 4x4/thr.
template <bool TANH>
__global__ __launch_bounds__(256) void gemm_bias_kernel(
    const float* __restrict__ A, const float* __restrict__ B,
    const float* __restrict__ bias, float* __restrict__ C,
    int M, int N, int K) {
    const int BM = 64, BN = 64, BK = 16;
    __shared__ float As[BK][BM + 4];   // padded: avoid stride-64 bank conflicts
    __shared__ float Bs[BK][BN];

    int tid = threadIdx.x;
    int tx = tid & 15;     // 16 col groups
    int ty = tid >> 4;     // 16 row groups
    int m0 = blockIdx.y * BM;
    int n0 = blockIdx.x * BN;

    // A-load mapping: float4 along K
    int arow = tid >> 2;               // 0..63
    int ak4  = (tid & 3) * 4;          // 0,4,8,12
    // B-load mapping: float4 along N
    int brow = tid >> 4;               // 0..15
    int bc4  = (tid & 15) * 4;         // 0..60

    float acc[4][4] = {};

    for (int k0 = 0; k0 < K; k0 += BK) {
        float4 av = make_float4(0.f, 0.f, 0.f, 0.f);
        int gr = m0 + arow;
        if (gr < M)
            av = *reinterpret_cast<const float4*>(A + (size_t)gr * K + k0 + ak4);
        As[ak4 + 0][arow] = av.x;
        As[ak4 + 1][arow] = av.y;
        As[ak4 + 2][arow] = av.z;
        As[ak4 + 3][arow] = av.w;

        float4 bv = *reinterpret_cast<const float4*>(B + (size_t)(k0 + brow) * N + n0 + bc4);
        *reinterpret_cast<float4*>(&Bs[brow][bc4]) = bv;

        __syncthreads();

        #pragma unroll
        for (int k = 0; k < BK; k++) {
            float a[4], b[4];
            #pragma unroll
            for (int i = 0; i < 4; i++) a[i] = As[k][ty * 4 + i];
            float4 b4 = *reinterpret_cast<const float4*>(&Bs[k][tx * 4]);
            b[0] = b4.x; b[1] = b4.y; b[2] = b4.z; b[3] = b4.w;
            #pragma unroll
            for (int i = 0; i < 4; i++)
                #pragma unroll
                for (int j = 0; j < 4; j++)
                    acc[i][j] = fmaf(a[i], b[j], acc[i][j]);
        }
        __syncthreads();
    }

    #pragma unroll
    for (int i = 0; i < 4; i++) {
        int gm = m0 + ty * 4 + i;
        if (gm >= M) continue;
        #pragma unroll
        for (int j = 0; j < 4; j++) {
            int gn = n0 + tx * 4 + j;
            float v = acc[i][j] + bias[gn];
            if (TANH) v = tanhf(v);
            C[(size_t)gm * N + gn] = v;
        }
    }
}

extern "C" void kernel_launch(void* const* d_in, const int* in_sizes, int n_in,
                              void* d_out, int out_size) {
    const float* news    = (const float*)d_in[0];
    const float* entf    = (const float*)d_in[1];
    const float* topf    = (const float*)d_in[2];
    const int*   ent_row = (const int*)d_in[3];
    const int*   ent_col = (const int*)d_in[4];
    const int*   top_row = (const int*)d_in[5];
    const int*   top_col = (const int*)d_in[6];
    const float* W1      = (const float*)d_in[7];
    const float* b1      = (const float*)d_in[8];
    const float* W2      = (const float*)d_in[9];
    const float* b2      = (const float*)d_in[10];
    float* out = (float*)d_out;
    int n_edges_ent = in_sizes[3];
    int n_edges_top = in_sizes[5];

    void *p_es, *p_ts, *p_ed, *p_td, *p_x, *p_h;
    cudaGetSymbolAddress(&p_es, g_ent_sum);
    cudaGetSymbolAddress(&p_ts, g_top_sum);
    cudaGetSymbolAddress(&p_ed, g_ent_deg);
    cudaGetSymbolAddress(&p_td, g_top_deg);
    cudaGetSymbolAddress(&p_x,  g_X);
    cudaGetSymbolAddress(&p_h,  g_H);

    cudaMemsetAsync(p_es, 0, sizeof(float) * (size_t)N_NEWS * DIM, 0);
    cudaMemsetAsync(p_ts, 0, sizeof(float) * (size_t)N_NEWS * DIM, 0);
    cudaMemsetAsync(p_ed, 0, sizeof(float) * N_NEWS, 0);
    cudaMemsetAsync(p_td, 0, sizeof(float) * N_NEWS, 0);

    // edge scatter: 8 warps (edges) per 256-thread block
    {
        int blocks = (n_edges_ent + 7) / 8;
        scatter_kernel<<<blocks, 256>>>(entf, ent_row, ent_col,
                                        (float*)p_es, (float*)p_ed, n_edges_ent);
    }
    {
        int blocks = (n_edges_top + 7) / 8;
        scatter_kernel<<<blocks, 256>>>(topf, top_row, top_col,
                                        (float*)p_ts, (float*)p_td, n_edges_top);
    }

    // build X
    {
        int total = N_NEWS * (KDIM / 4);
        int blocks = (total + 255) / 256;
        build_x_kernel<<<blocks, 256>>>(news);
    }

    // GEMM1: H = tanh(X @ W1 + b1)   [100000,384]x[384,512]
    {
        dim3 grid(HIDN / 64, (N_NEWS + 63) / 64);
        gemm_bias_kernel<true><<<grid, 256>>>((const float*)p_x, W1, b1,
                                              (float*)p_h, N_NEWS, HIDN, KDIM);
    }
    // GEMM2: out = H @ W2 + b2       [100000,512]x[512,128]
    {
        dim3 grid(OUTD / 64, (N_NEWS + 63) / 64);
        gemm_bias_kernel<false><<<grid, 256>>>((const float*)p_h, W2, b2,
                                               out, N_NEWS, OUTD, HIDN);
    }
}

// round 5
// speedup vs baseline: 2.1575x; 2.1575x over previous
#include <cuda_runtime.h>
#include <cuda_bf16.h>
#include <cstdint>
#include <cstddef>

#define N_NEWS 100000
#define DIM    128
#define KDIM   384   // 3*DIM
#define HIDN   512
#define OUTD   128

// ---------------- scratch (__device__ globals: allocation-free rule) -------
__device__ float g_ent_sum[(size_t)N_NEWS * DIM];
__device__ float g_top_sum[(size_t)N_NEWS * DIM];
__device__ float g_ent_deg[N_NEWS];
__device__ float g_top_deg[N_NEWS];
__device__ __nv_bfloat16 g_X_hi[(size_t)N_NEWS * KDIM];
__device__ __nv_bfloat16 g_X_lo[(size_t)N_NEWS * KDIM];
__device__ __nv_bfloat16 g_H_hi[(size_t)N_NEWS * HIDN];
__device__ __nv_bfloat16 g_H_lo[(size_t)N_NEWS * HIDN];
__device__ __nv_bfloat16 g_W1t_hi[(size_t)HIDN * KDIM];   // [N=512][K=384]
__device__ __nv_bfloat16 g_W1t_lo[(size_t)HIDN * KDIM];
__device__ __nv_bfloat16 g_W2t_hi[(size_t)OUTD * HIDN];   // [N=128][K=512]
__device__ __nv_bfloat16 g_W2t_lo[(size_t)OUTD * HIDN];

// ---------------- helpers --------------------------------------------------
__device__ __forceinline__ uint32_t smem_to_u32(const void* p) {
    uint32_t a;
    asm("{ .reg .u64 t; cvta.to.shared.u64 t, %1; cvt.u32.u64 %0, t; }"
        : "=r"(a) : "l"(p));
    return a;
}

__device__ __forceinline__ void ldsm_x4(uint32_t* r, uint32_t addr) {
    asm volatile("ldmatrix.sync.aligned.m8n8.x4.shared.b16 {%0,%1,%2,%3}, [%4];"
                 : "=r"(r[0]), "=r"(r[1]), "=r"(r[2]), "=r"(r[3]) : "r"(addr));
}
__device__ __forceinline__ void mma_bf16(float* d, const uint32_t* a,
                                         const uint32_t* b) {
    asm volatile(
        "mma.sync.aligned.m16n8k16.row.col.f32.bf16.bf16.f32 "
        "{%0,%1,%2,%3}, {%4,%5,%6,%7}, {%8,%9}, {%0,%1,%2,%3};"
        : "+f"(d[0]), "+f"(d[1]), "+f"(d[2]), "+f"(d[3])
        : "r"(a[0]), "r"(a[1]), "r"(a[2]), "r"(a[3]), "r"(b[0]), "r"(b[1]));
}

__device__ __forceinline__ void split_bf16(float x, __nv_bfloat16& h, __nv_bfloat16& l) {
    h = __float2bfloat16(x);
    l = __float2bfloat16(x - __bfloat162float(h));
}

// swizzled byte offset inside a [128 rows x 128B] tile
__device__ __forceinline__ uint32_t sw_off(int row, int chunk16) {
    return (uint32_t)row * 128u + (uint32_t)((chunk16 ^ (row & 7)) << 4);
}

// -------------------- edge scatter: one warp per edge ----------------------
__global__ void scatter_kernel(const float* __restrict__ feats,
                               const int*  __restrict__ row,
                               const int*  __restrict__ col,
                               float* __restrict__ sum,
                               float* __restrict__ deg,
                               int n_edges) {
    int warp = (blockIdx.x * blockDim.x + threadIdx.x) >> 5;
    int lane = threadIdx.x & 31;
    if (warp >= n_edges) return;
    int r = row[warp];
    int c = col[warp];
    float4 v = reinterpret_cast<const float4*>(feats + (size_t)c * DIM)[lane];
    float* dst = sum + (size_t)r * DIM + lane * 4;
    asm volatile("red.global.add.v4.f32 [%0], {%1, %2, %3, %4};"
                 :: "l"(dst), "f"(v.x), "f"(v.y), "f"(v.z), "f"(v.w) : "memory");
    if (lane == 0) atomicAdd(deg + r, 1.0f);
}

// ------------- build X = [news | ent_sum/deg | top_sum/deg] as bf16 hi/lo --
__global__ void build_x_kernel(const float* __restrict__ news) {
    int idx = blockIdx.x * blockDim.x + threadIdx.x;  // float4 index
    const int F4_PER_ROW = KDIM / 4;                  // 96
    if (idx >= N_NEWS * F4_PER_ROW) return;
    int r  = idx / F4_PER_ROW;
    int j4 = idx - r * F4_PER_ROW;
    float4 v;
    if (j4 < 32) {
        v = reinterpret_cast<const float4*>(news)[(size_t)r * 32 + j4];
    } else if (j4 < 64) {
        float inv = 1.0f / (g_ent_deg[r] + 1e-8f);
        float4 s = reinterpret_cast<const float4*>(g_ent_sum)[(size_t)r * 32 + (j4 - 32)];
        v = make_float4(s.x * inv, s.y * inv, s.z * inv, s.w * inv);
    } else {
        float inv = 1.0f / (g_top_deg[r] + 1e-8f);
        float4 s = reinterpret_cast<const float4*>(g_top_sum)[(size_t)r * 32 + (j4 - 64)];
        v = make_float4(s.x * inv, s.y * inv, s.z * inv, s.w * inv);
    }
    __nv_bfloat16 h[4], l[4];
    split_bf16(v.x, h[0], l[0]);
    split_bf16(v.y, h[1], l[1]);
    split_bf16(v.z, h[2], l[2]);
    split_bf16(v.w, h[3], l[3]);
    *reinterpret_cast<uint2*>(&g_X_hi[(size_t)idx * 4]) = *reinterpret_cast<uint2*>(h);
    *reinterpret_cast<uint2*>(&g_X_lo[(size_t)idx * 4]) = *reinterpret_cast<uint2*>(l);
}

// ---------------- weight transpose + split to bf16 hi/lo -------------------
__global__ void prep_w_kernel(const float* __restrict__ W, __nv_bfloat16* Wt_hi,
                              __nv_bfloat16* Wt_lo, int K, int N) {
    int idx = blockIdx.x * blockDim.x + threadIdx.x;
    if (idx >= K * N) return;
    int k = idx / N, n = idx - k * N;
    __nv_bfloat16 h, l;
    split_bf16(W[idx], h, l);
    Wt_hi[(size_t)n * K + k] = h;
    Wt_lo[(size_t)n * K + k] = l;
}

// ---------------- mma.sync split-bf16 GEMM: C = act(A@B^T + bias) ----------
// A (hi/lo): [M][Kfull] bf16 row-major; B (hi/lo): [Ntot][Kfull] bf16 row-major.
// CTA tile 128x128, K-chunk 64. 8 warps of 64x32. 64KB dynamic smem.
#define TILE_BYTES 16384
#define GEMM_SMEM  (4 * TILE_BYTES)

template <bool TANH, bool SPLIT_OUT>
__global__ __launch_bounds__(256, 2) void gemm_mma_kernel(
    const __nv_bfloat16* __restrict__ Ah, const __nv_bfloat16* __restrict__ Al,
    const __nv_bfloat16* __restrict__ Bh, const __nv_bfloat16* __restrict__ Bl,
    const float* __restrict__ bias,
    float* __restrict__ outF, __nv_bfloat16* __restrict__ outH,
    __nv_bfloat16* __restrict__ outL,
    int M, int Ntot, int Kfull) {
    extern __shared__ __align__(1024) char smem[];
    const uint32_t s_ah = smem_to_u32(smem);
    const uint32_t s_al = s_ah + TILE_BYTES;
    const uint32_t s_bh = s_al + TILE_BYTES;
    const uint32_t s_bl = s_bh + TILE_BYTES;

    const int tid  = threadIdx.x;
    const int wid  = tid >> 5;
    const int lane = tid & 31;
    const int wm   = wid & 1;   // 2 m-groups of 64
    const int wn   = wid >> 1;  // 4 n-groups of 32
    const int m0   = blockIdx.y * 128;
    const int n0   = blockIdx.x * 128;

    float acc[4][4][4] = {};  // [mi][ni][frag]

    // loader mapping (per 256-thr pass over one 128x128B tile)
    const int lrow = tid >> 1;            // 0..127, two threads per row
    const int lseg = (tid & 1) * 4;       // chunks 0-3 or 4-7

    // ldmatrix address components (x4: lanes 0-7 -> mat0, 8-15 -> mat1, ...)
    const int a_row = (lane & 7) + ((lane >> 3) & 1) * 8;  // 0..15
    const int a_ch  = lane >> 4;                            // 0..1
    const int b_row = (lane & 7) + ((lane >> 4) & 1) * 8;   // 0..15
    const int b_ch  = (lane >> 3) & 1;                      // 0..1

    const int n_chunks = Kfull >> 6;
    for (int ch = 0; ch < n_chunks; ch++) {
        const int k0 = ch << 6;
        // ---- fill 4 tiles: each thread stores 4 x 16B per tile ----
        {
            int gr = m0 + lrow;
            size_t aoff = (size_t)gr * Kfull + k0 + lseg * 8;
            size_t boff = (size_t)(n0 + lrow) * Kfull + k0 + lseg * 8;
            #pragma unroll
            for (int s = 0; s < 4; s++) {
                uint32_t so = sw_off(lrow, lseg + s);
                uint4 vah = make_uint4(0, 0, 0, 0), val = make_uint4(0, 0, 0, 0);
                if (gr < M) {
                    vah = *reinterpret_cast<const uint4*>(Ah + aoff + s * 8);
                    val = *reinterpret_cast<const uint4*>(Al + aoff + s * 8);
                }
                *reinterpret_cast<uint4*>(smem + so)              = vah;
                *reinterpret_cast<uint4*>(smem + TILE_BYTES + so) = val;
                *reinterpret_cast<uint4*>(smem + 2 * TILE_BYTES + so) =
                    *reinterpret_cast<const uint4*>(Bh + boff + s * 8);
                *reinterpret_cast<uint4*>(smem + 3 * TILE_BYTES + so) =
                    *reinterpret_cast<const uint4*>(Bl + boff + s * 8);
            }
        }
        __syncthreads();

        // ---- compute: 4 k16 steps ----
        #pragma unroll
        for (int kk = 0; kk < 4; kk++) {
            uint32_t afrag[4][4];   // hi A frags per mi
            uint32_t bh[2][4], bl[2][4];
            // B hi/lo: [N][K] row-major + .col layout => NON-trans ldmatrix
            #pragma unroll
            for (int g2 = 0; g2 < 2; g2++) {
                int nr = wn * 32 + g2 * 16 + b_row;
                uint32_t so = sw_off(nr, 2 * kk + b_ch);
                ldsm_x4(bh[g2], s_bh + so);
                ldsm_x4(bl[g2], s_bl + so);
            }
            // A hi
            #pragma unroll
            for (int mi = 0; mi < 4; mi++) {
                int mr = wm * 64 + mi * 16 + a_row;
                ldsm_x4(afrag[mi], s_ah + sw_off(mr, 2 * kk + a_ch));
            }
            // hi*hi and hi*lo
            #pragma unroll
            for (int mi = 0; mi < 4; mi++)
                #pragma unroll
                for (int ni = 0; ni < 4; ni++) {
                    const uint32_t* bfh = &bh[ni >> 1][(ni & 1) * 2];
                    const uint32_t* bfl = &bl[ni >> 1][(ni & 1) * 2];
                    mma_bf16(acc[mi][ni], afrag[mi], bfh);
                    mma_bf16(acc[mi][ni], afrag[mi], bfl);
                }
            // A lo (overwrite), then lo*hi
            #pragma unroll
            for (int mi = 0; mi < 4; mi++) {
                int mr = wm * 64 + mi * 16 + a_row;
                ldsm_x4(afrag[mi], s_al + sw_off(mr, 2 * kk + a_ch));
            }
            #pragma unroll
            for (int mi = 0; mi < 4; mi++)
                #pragma unroll
                for (int ni = 0; ni < 4; ni++) {
                    const uint32_t* bfh = &bh[ni >> 1][(ni & 1) * 2];
                    mma_bf16(acc[mi][ni], afrag[mi], bfh);
                }
        }
        __syncthreads();
    }

    // ---- epilogue ----
    const int g = lane >> 2;
    const int q = lane & 3;
    #pragma unroll
    for (int mi = 0; mi < 4; mi++) {
        #pragma unroll
        for (int ni = 0; ni < 4; ni++) {
            int col = n0 + wn * 32 + ni * 8 + q * 2;
            float bia0 = bias[col], bia1 = bias[col + 1];
            #pragma unroll
            for (int half = 0; half < 2; half++) {
                int gm = m0 + wm * 64 + mi * 16 + g + half * 8;
                if (gm >= M) continue;
                float v0 = acc[mi][ni][half * 2 + 0] + bia0;
                float v1 = acc[mi][ni][half * 2 + 1] + bia1;
                if (TANH) { v0 = tanhf(v0); v1 = tanhf(v1); }
                size_t o = (size_t)gm * Ntot + col;
                if (SPLIT_OUT) {
                    __nv_bfloat16 h0, l0, h1, l1;
                    split_bf16(v0, h0, l0);
                    split_bf16(v1, h1, l1);
                    outH[o] = h0; outH[o + 1] = h1;
                    outL[o] = l0; outL[o + 1] = l1;
                } else {
                    outF[o] = v0; outF[o + 1] = v1;
                }
            }
        }
    }
}

// ---------------------------------------------------------------------------
extern "C" void kernel_launch(void* const* d_in, const int* in_sizes, int n_in,
                              void* d_out, int out_size) {
    const float* news    = (const float*)d_in[0];
    const float* entf    = (const float*)d_in[1];
    const float* topf    = (const float*)d_in[2];
    const int*   ent_row = (const int*)d_in[3];
    const int*   ent_col = (const int*)d_in[4];
    const int*   top_row = (const int*)d_in[5];
    const int*   top_col = (const int*)d_in[6];
    const float* W1      = (const float*)d_in[7];
    const float* b1      = (const float*)d_in[8];
    const float* W2      = (const float*)d_in[9];
    const float* b2      = (const float*)d_in[10];
    float* out = (float*)d_out;
    int n_edges_ent = in_sizes[3];
    int n_edges_top = in_sizes[5];

    void *p_es, *p_ts, *p_ed, *p_td;
    void *p_xh, *p_xl, *p_hh, *p_hl, *p_w1h, *p_w1l, *p_w2h, *p_w2l;
    cudaGetSymbolAddress(&p_es, g_ent_sum);
    cudaGetSymbolAddress(&p_ts, g_top_sum);
    cudaGetSymbolAddress(&p_ed, g_ent_deg);
    cudaGetSymbolAddress(&p_td, g_top_deg);
    cudaGetSymbolAddress(&p_xh, g_X_hi);
    cudaGetSymbolAddress(&p_xl, g_X_lo);
    cudaGetSymbolAddress(&p_hh, g_H_hi);
    cudaGetSymbolAddress(&p_hl, g_H_lo);
    cudaGetSymbolAddress(&p_w1h, g_W1t_hi);
    cudaGetSymbolAddress(&p_w1l, g_W1t_lo);
    cudaGetSymbolAddress(&p_w2h, g_W2t_hi);
    cudaGetSymbolAddress(&p_w2l, g_W2t_lo);

    cudaFuncSetAttribute(gemm_mma_kernel<true, true>,
                         cudaFuncAttributeMaxDynamicSharedMemorySize, GEMM_SMEM);
    cudaFuncSetAttribute(gemm_mma_kernel<false, false>,
                         cudaFuncAttributeMaxDynamicSharedMemorySize, GEMM_SMEM);

    cudaMemsetAsync(p_es, 0, sizeof(float) * (size_t)N_NEWS * DIM, 0);
    cudaMemsetAsync(p_ts, 0, sizeof(float) * (size_t)N_NEWS * DIM, 0);
    cudaMemsetAsync(p_ed, 0, sizeof(float) * N_NEWS, 0);
    cudaMemsetAsync(p_td, 0, sizeof(float) * N_NEWS, 0);

    // edge scatter: 8 warps (edges) per 256-thread block
    {
        int blocks = (n_edges_ent + 7) / 8;
        scatter_kernel<<<blocks, 256>>>(entf, ent_row, ent_col,
                                        (float*)p_es, (float*)p_ed, n_edges_ent);
    }
    {
        int blocks = (n_edges_top + 7) / 8;
        scatter_kernel<<<blocks, 256>>>(topf, top_row, top_col,
                                        (float*)p_ts, (float*)p_td, n_edges_top);
    }

    // weight prep (tiny)
    {
        int tot = KDIM * HIDN;
        prep_w_kernel<<<(tot + 255) / 256, 256>>>(
            W1, (__nv_bfloat16*)p_w1h, (__nv_bfloat16*)p_w1l, KDIM, HIDN);
    }
    {
        int tot = HIDN * OUTD;
        prep_w_kernel<<<(tot + 255) / 256, 256>>>(
            W2, (__nv_bfloat16*)p_w2h, (__nv_bfloat16*)p_w2l, HIDN, OUTD);
    }

    // build X (bf16 hi/lo)
    {
        int total = N_NEWS * (KDIM / 4);
        build_x_kernel<<<(total + 255) / 256, 256>>>(news);
    }

    const int m_tiles = (N_NEWS + 127) / 128;  // 782

    // GEMM1: H = tanh(X @ W1 + b1)   [100000,384] x [384,512]
    {
        dim3 grid(HIDN / 128, m_tiles);
        gemm_mma_kernel<true, true><<<grid, 256, GEMM_SMEM>>>(
            (const __nv_bfloat16*)p_xh, (const __nv_bfloat16*)p_xl,
            (const __nv_bfloat16*)p_w1h, (const __nv_bfloat16*)p_w1l,
            b1, nullptr, (__nv_bfloat16*)p_hh, (__nv_bfloat16*)p_hl,
            N_NEWS, HIDN, KDIM);
    }
    // GEMM2: out = H @ W2 + b2       [100000,512] x [512,128]
    {
        dim3 grid(OUTD / 128, m_tiles);
        gemm_mma_kernel<false, false><<<grid, 256, GEMM_SMEM>>>(
            (const __nv_bfloat16*)p_hh, (const __nv_bfloat16*)p_hl,
            (const __nv_bfloat16*)p_w2h, (const __nv_bfloat16*)p_w2l,
            b2, out, nullptr, nullptr,
            N_NEWS, OUTD, HIDN);
    }
}

// round 7
// speedup vs baseline: 2.8365x; 1.3147x over previous
#include <cuda_runtime.h>
#include <cuda_bf16.h>
#include <cstdint>
#include <cstddef>

#define N_NEWS 100000
#define DIM    128
#define KDIM   384   // 3*DIM
#define HIDN   512
#define OUTD   128
#define MAX_EDGES 1600000
#define NTOT2  (2 * N_NEWS)

// ---------------- scratch (__device__ globals: allocation-free rule) -------
__device__ int g_cnt[NTOT2];        // per-row edge counts (ent | top)
__device__ int g_rowstart[NTOT2];   // exclusive prefix (joint)
__device__ int g_cursor[NTOT2];     // fill cursors
__device__ int g_bsum[256];         // scan block sums
__device__ int g_csr_col[2 * MAX_EDGES];

__device__ __nv_bfloat16 g_X_hi[(size_t)N_NEWS * KDIM];
__device__ __nv_bfloat16 g_X_lo[(size_t)N_NEWS * KDIM];
__device__ __nv_bfloat16 g_H_hi[(size_t)N_NEWS * HIDN];
__device__ __nv_bfloat16 g_H_lo[(size_t)N_NEWS * HIDN];
__device__ __nv_bfloat16 g_W1t_hi[(size_t)HIDN * KDIM];   // [N=512][K=384]
__device__ __nv_bfloat16 g_W1t_lo[(size_t)HIDN * KDIM];
__device__ __nv_bfloat16 g_W2t_hi[(size_t)OUTD * HIDN];   // [N=128][K=512]
__device__ __nv_bfloat16 g_W2t_lo[(size_t)OUTD * HIDN];

// ---------------- helpers --------------------------------------------------
__device__ __forceinline__ uint32_t smem_to_u32(const void* p) {
    uint32_t a;
    asm("{ .reg .u64 t; cvta.to.shared.u64 t, %1; cvt.u32.u64 %0, t; }"
        : "=r"(a) : "l"(p));
    return a;
}

__device__ __forceinline__ void ldsm_x4(uint32_t* r, uint32_t addr) {
    asm volatile("ldmatrix.sync.aligned.m8n8.x4.shared.b16 {%0,%1,%2,%3}, [%4];"
                 : "=r"(r[0]), "=r"(r[1]), "=r"(r[2]), "=r"(r[3]) : "r"(addr));
}
__device__ __forceinline__ void mma_bf16(float* d, const uint32_t* a,
                                         const uint32_t* b) {
    asm volatile(
        "mma.sync.aligned.m16n8k16.row.col.f32.bf16.bf16.f32 "
        "{%0,%1,%2,%3}, {%4,%5,%6,%7}, {%8,%9}, {%0,%1,%2,%3};"
        : "+f"(d[0]), "+f"(d[1]), "+f"(d[2]), "+f"(d[3])
        : "r"(a[0]), "r"(a[1]), "r"(a[2]), "r"(a[3]), "r"(b[0]), "r"(b[1]));
}

__device__ __forceinline__ void split_bf16(float x, __nv_bfloat16& h, __nv_bfloat16& l) {
    h = __float2bfloat16(x);
    l = __float2bfloat16(x - __bfloat162float(h));
}

// swizzled byte offset inside a [128 rows x 128B] tile
__device__ __forceinline__ uint32_t sw_off(int row, int chunk16) {
    return (uint32_t)row * 128u + (uint32_t)((chunk16 ^ (row & 7)) << 4);
}

// ==================== CSR build ============================================
__global__ void hist_kernel(const int* __restrict__ row, int n, int base) {
    int i = blockIdx.x * blockDim.x + threadIdx.x;
    if (i < n) atomicAdd(&g_cnt[base + row[i]], 1);
}

// scan1: 196 blocks x 256 thr, 4 elems/thr -> per-block exclusive + block sum
__global__ void scan1_kernel(int M) {
    __shared__ int sh[256];
    int t = threadIdx.x, b = blockIdx.x;
    int base = b * 1024 + t * 4;
    int v0 = 0, v1 = 0, v2 = 0, v3 = 0;
    if (base + 0 < M) v0 = g_cnt[base + 0];
    if (base + 1 < M) v1 = g_cnt[base + 1];
    if (base + 2 < M) v2 = g_cnt[base + 2];
    if (base + 3 < M) v3 = g_cnt[base + 3];
    sh[t] = v0 + v1 + v2 + v3;
    __syncthreads();
    #pragma unroll
    for (int off = 1; off < 256; off <<= 1) {
        int x = 0;
        if (t >= off) x = sh[t - off];
        __syncthreads();
        if (t >= off) sh[t] += x;
        __syncthreads();
    }
    int run = (t > 0) ? sh[t - 1] : 0;
    if (base + 0 < M) g_rowstart[base + 0] = run; run += v0;
    if (base + 1 < M) g_rowstart[base + 1] = run; run += v1;
    if (base + 2 < M) g_rowstart[base + 2] = run; run += v2;
    if (base + 3 < M) g_rowstart[base + 3] = run;
    if (t == 255) g_bsum[b] = sh[255];
}

// scan2: single block scans block sums (exclusive, in place)
__global__ void scan2_kernel(int nb) {
    __shared__ int sh[256];
    int t = threadIdx.x;
    int v = (t < nb) ? g_bsum[t] : 0;
    sh[t] = v;
    __syncthreads();
    #pragma unroll
    for (int off = 1; off < 256; off <<= 1) {
        int x = 0;
        if (t >= off) x = sh[t - off];
        __syncthreads();
        if (t >= off) sh[t] += x;
        __syncthreads();
    }
    if (t < nb) g_bsum[t] = (t > 0) ? sh[t - 1] : 0;
}

// scan3: add block offsets, init cursors
__global__ void scan3_kernel(int M) {
    int i = blockIdx.x * blockDim.x + threadIdx.x;
    if (i < M) {
        int v = g_rowstart[i] + g_bsum[i >> 10];
        g_rowstart[i] = v;
        g_cursor[i] = v;
    }
}

__global__ void fill_kernel(const int* __restrict__ row,
                            const int* __restrict__ col, int n, int base) {
    int i = blockIdx.x * blockDim.x + threadIdx.x;
    if (i < n) {
        int p = atomicAdd(&g_cursor[base + row[i]], 1);
        g_csr_col[p] = col[i];
    }
}

// ==================== gather: one warp per news row ========================
__device__ __forceinline__ void store_split4(int r, int colb, float4 v) {
    __nv_bfloat16 h[4], l[4];
    split_bf16(v.x, h[0], l[0]);
    split_bf16(v.y, h[1], l[1]);
    split_bf16(v.z, h[2], l[2]);
    split_bf16(v.w, h[3], l[3]);
    size_t o = (size_t)r * KDIM + colb;
    *reinterpret_cast<uint2*>(&g_X_hi[o]) = *reinterpret_cast<uint2*>(h);
    *reinterpret_cast<uint2*>(&g_X_lo[o]) = *reinterpret_cast<uint2*>(l);
}

__device__ __forceinline__ void agg_part(const float* __restrict__ feats,
                                         int s, int c, int r, int colb,
                                         int lane) {
    float a0 = 0.f, a1 = 0.f, a2 = 0.f, a3 = 0.f;
    float b0 = 0.f, b1 = 0.f, b2 = 0.f, b3 = 0.f;
    int j = 0;
    for (; j + 2 <= c; j += 2) {
        int c0 = g_csr_col[s + j];
        int c1 = g_csr_col[s + j + 1];
        float4 f0 = reinterpret_cast<const float4*>(feats)[(size_t)c0 * 32 + lane];
        float4 f1 = reinterpret_cast<const float4*>(feats)[(size_t)c1 * 32 + lane];
        a0 += f0.x; a1 += f0.y; a2 += f0.z; a3 += f0.w;
        b0 += f1.x; b1 += f1.y; b2 += f1.z; b3 += f1.w;
    }
    if (j < c) {
        int c0 = g_csr_col[s + j];
        float4 f0 = reinterpret_cast<const float4*>(feats)[(size_t)c0 * 32 + lane];
        a0 += f0.x; a1 += f0.y; a2 += f0.z; a3 += f0.w;
    }
    float inv = 1.0f / ((float)c + 1e-8f);
    float4 v = make_float4((a0 + b0) * inv, (a1 + b1) * inv,
                           (a2 + b2) * inv, (a3 + b3) * inv);
    store_split4(r, colb, v);
}

__global__ __launch_bounds__(256) void gather_kernel(
    const float* __restrict__ news, const float* __restrict__ entf,
    const float* __restrict__ topf) {
    int gw   = (blockIdx.x * blockDim.x + threadIdx.x) >> 5;
    int lane = threadIdx.x & 31;
    if (gw >= N_NEWS) return;
    // news copy -> cols [0,128)
    float4 v = reinterpret_cast<const float4*>(news)[(size_t)gw * 32 + lane];
    store_split4(gw, lane * 4, v);
    // entity mean -> cols [128,256)
    agg_part(entf, g_rowstart[gw], g_cnt[gw], gw, 128 + lane * 4, lane);
    // topic mean -> cols [256,384)
    agg_part(topf, g_rowstart[N_NEWS + gw], g_cnt[N_NEWS + gw], gw,
             256 + lane * 4, lane);
}

// ---------------- weight transpose + split to bf16 hi/lo -------------------
__global__ void prep_w_kernel(const float* __restrict__ W, __nv_bfloat16* Wt_hi,
                              __nv_bfloat16* Wt_lo, int K, int N) {
    int idx = blockIdx.x * blockDim.x + threadIdx.x;
    if (idx >= K * N) return;
    int k = idx / N, n = idx - k * N;
    __nv_bfloat16 h, l;
    split_bf16(W[idx], h, l);
    Wt_hi[(size_t)n * K + k] = h;
    Wt_lo[(size_t)n * K + k] = l;
}

// ---------------- mma.sync split-bf16 GEMM: C = act(A@B^T + bias) ----------
#define TILE_BYTES 16384
#define GEMM_SMEM  (4 * TILE_BYTES)

template <bool TANH, bool SPLIT_OUT>
__global__ __launch_bounds__(256, 2) void gemm_mma_kernel(
    const __nv_bfloat16* __restrict__ Ah, const __nv_bfloat16* __restrict__ Al,
    const __nv_bfloat16* __restrict__ Bh, const __nv_bfloat16* __restrict__ Bl,
    const float* __restrict__ bias,
    float* __restrict__ outF, __nv_bfloat16* __restrict__ outH,
    __nv_bfloat16* __restrict__ outL,
    int M, int Ntot, int Kfull) {
    extern __shared__ __align__(1024) char smem[];
    const uint32_t s_ah = smem_to_u32(smem);
    const uint32_t s_al = s_ah + TILE_BYTES;
    const uint32_t s_bh = s_al + TILE_BYTES;
    const uint32_t s_bl = s_bh + TILE_BYTES;

    const int tid  = threadIdx.x;
    const int wid  = tid >> 5;
    const int lane = tid & 31;
    const int wm   = wid & 1;   // 2 m-groups of 64
    const int wn   = wid >> 1;  // 4 n-groups of 32
    const int m0   = blockIdx.y * 128;
    const int n0   = blockIdx.x * 128;

    float acc[4][4][4] = {};  // [mi][ni][frag]

    const int lrow = tid >> 1;
    const int lseg = (tid & 1) * 4;

    const int a_row = (lane & 7) + ((lane >> 3) & 1) * 8;
    const int a_ch  = lane >> 4;
    const int b_row = (lane & 7) + ((lane >> 4) & 1) * 8;
    const int b_ch  = (lane >> 3) & 1;

    const int n_chunks = Kfull >> 6;
    for (int ch = 0; ch < n_chunks; ch++) {
        const int k0 = ch << 6;
        {
            int gr = m0 + lrow;
            size_t aoff = (size_t)gr * Kfull + k0 + lseg * 8;
            size_t boff = (size_t)(n0 + lrow) * Kfull + k0 + lseg * 8;
            #pragma unroll
            for (int s = 0; s < 4; s++) {
                uint32_t so = sw_off(lrow, lseg + s);
                uint4 vah = make_uint4(0, 0, 0, 0), val = make_uint4(0, 0, 0, 0);
                if (gr < M) {
                    vah = *reinterpret_cast<const uint4*>(Ah + aoff + s * 8);
                    val = *reinterpret_cast<const uint4*>(Al + aoff + s * 8);
                }
                *reinterpret_cast<uint4*>(smem + so)              = vah;
                *reinterpret_cast<uint4*>(smem + TILE_BYTES + so) = val;
                *reinterpret_cast<uint4*>(smem + 2 * TILE_BYTES + so) =
                    *reinterpret_cast<const uint4*>(Bh + boff + s * 8);
                *reinterpret_cast<uint4*>(smem + 3 * TILE_BYTES + so) =
                    *reinterpret_cast<const uint4*>(Bl + boff + s * 8);
            }
        }
        __syncthreads();

        #pragma unroll
        for (int kk = 0; kk < 4; kk++) {
            uint32_t afrag[4][4];
            uint32_t bh[2][4], bl[2][4];
            #pragma unroll
            for (int g2 = 0; g2 < 2; g2++) {
                int nr = wn * 32 + g2 * 16 + b_row;
                uint32_t so = sw_off(nr, 2 * kk + b_ch);
                ldsm_x4(bh[g2], s_bh + so);
                ldsm_x4(bl[g2], s_bl + so);
            }
            #pragma unroll
            for (int mi = 0; mi < 4; mi++) {
                int mr = wm * 64 + mi * 16 + a_row;
                ldsm_x4(afrag[mi], s_ah + sw_off(mr, 2 * kk + a_ch));
            }
            #pragma unroll
            for (int mi = 0; mi < 4; mi++)
                #pragma unroll
                for (int ni = 0; ni < 4; ni++) {
                    const uint32_t* bfh = &bh[ni >> 1][(ni & 1) * 2];
                    const uint32_t* bfl = &bl[ni >> 1][(ni & 1) * 2];
                    mma_bf16(acc[mi][ni], afrag[mi], bfh);
                    mma_bf16(acc[mi][ni], afrag[mi], bfl);
                }
            #pragma unroll
            for (int mi = 0; mi < 4; mi++) {
                int mr = wm * 64 + mi * 16 + a_row;
                ldsm_x4(afrag[mi], s_al + sw_off(mr, 2 * kk + a_ch));
            }
            #pragma unroll
            for (int mi = 0; mi < 4; mi++)
                #pragma unroll
                for (int ni = 0; ni < 4; ni++) {
                    const uint32_t* bfh = &bh[ni >> 1][(ni & 1) * 2];
                    mma_bf16(acc[mi][ni], afrag[mi], bfh);
                }
        }
        __syncthreads();
    }

    const int g = lane >> 2;
    const int q = lane & 3;
    #pragma unroll
    for (int mi = 0; mi < 4; mi++) {
        #pragma unroll
        for (int ni = 0; ni < 4; ni++) {
            int col = n0 + wn * 32 + ni * 8 + q * 2;
            float bia0 = bias[col], bia1 = bias[col + 1];
            #pragma unroll
            for (int half = 0; half < 2; half++) {
                int gm = m0 + wm * 64 + mi * 16 + g + half * 8;
                if (gm >= M) continue;
                float v0 = acc[mi][ni][half * 2 + 0] + bia0;
                float v1 = acc[mi][ni][half * 2 + 1] + bia1;
                if (TANH) { v0 = tanhf(v0); v1 = tanhf(v1); }
                size_t o = (size_t)gm * Ntot + col;
                if (SPLIT_OUT) {
                    __nv_bfloat16 h0, l0, h1, l1;
                    split_bf16(v0, h0, l0);
                    split_bf16(v1, h1, l1);
                    outH[o] = h0; outH[o + 1] = h1;
                    outL[o] = l0; outL[o + 1] = l1;
                } else {
                    outF[o] = v0; outF[o + 1] = v1;
                }
            }
        }
    }
}

// ---------------------------------------------------------------------------
extern "C" void kernel_launch(void* const* d_in, const int* in_sizes, int n_in,
                              void* d_out, int out_size) {
    const float* news    = (const float*)d_in[0];
    const float* entf    = (const float*)d_in[1];
    const float* topf    = (const float*)d_in[2];
    const int*   ent_row = (const int*)d_in[3];
    const int*   ent_col = (const int*)d_in[4];
    const int*   top_row = (const int*)d_in[5];
    const int*   top_col = (const int*)d_in[6];
    const float* W1      = (const float*)d_in[7];
    const float* b1      = (const float*)d_in[8];
    const float* W2      = (const float*)d_in[9];
    const float* b2      = (const float*)d_in[10];
    float* out = (float*)d_out;
    int n_ent = in_sizes[3];
    int n_top = in_sizes[5];

    void *p_cnt, *p_hh, *p_hl, *p_w1h, *p_w1l, *p_w2h, *p_w2l, *p_xh, *p_xl;
    cudaGetSymbolAddress(&p_cnt, g_cnt);
    cudaGetSymbolAddress(&p_xh, g_X_hi);
    cudaGetSymbolAddress(&p_xl, g_X_lo);
    cudaGetSymbolAddress(&p_hh, g_H_hi);
    cudaGetSymbolAddress(&p_hl, g_H_lo);
    cudaGetSymbolAddress(&p_w1h, g_W1t_hi);
    cudaGetSymbolAddress(&p_w1l, g_W1t_lo);
    cudaGetSymbolAddress(&p_w2h, g_W2t_hi);
    cudaGetSymbolAddress(&p_w2l, g_W2t_lo);

    cudaFuncSetAttribute(gemm_mma_kernel<true, true>,
                         cudaFuncAttributeMaxDynamicSharedMemorySize, GEMM_SMEM);
    cudaFuncSetAttribute(gemm_mma_kernel<false, false>,
                         cudaFuncAttributeMaxDynamicSharedMemorySize, GEMM_SMEM);

    // ---- CSR build ----
    cudaMemsetAsync(p_cnt, 0, sizeof(int) * NTOT2, 0);
    hist_kernel<<<(n_ent + 255) / 256, 256>>>(ent_row, n_ent, 0);
    hist_kernel<<<(n_top + 255) / 256, 256>>>(top_row, n_top, N_NEWS);
    const int M2 = NTOT2;
    const int nb = (M2 + 1023) / 1024;  // 196
    scan1_kernel<<<nb, 256>>>(M2);
    scan2_kernel<<<1, 256>>>(nb);
    scan3_kernel<<<(M2 + 255) / 256, 256>>>(M2);
    fill_kernel<<<(n_ent + 255) / 256, 256>>>(ent_row, ent_col, n_ent, 0);
    fill_kernel<<<(n_top + 255) / 256, 256>>>(top_row, top_col, n_top, N_NEWS);

    // ---- weight prep (tiny) ----
    prep_w_kernel<<<(KDIM * HIDN + 255) / 256, 256>>>(
        W1, (__nv_bfloat16*)p_w1h, (__nv_bfloat16*)p_w1l, KDIM, HIDN);
    prep_w_kernel<<<(HIDN * OUTD + 255) / 256, 256>>>(
        W2, (__nv_bfloat16*)p_w2h, (__nv_bfloat16*)p_w2l, HIDN, OUTD);

    // ---- gather: build X directly (news copy + two means) ----
    {
        int warps = N_NEWS;
        int blocks = (warps * 32 + 255) / 256;
        gather_kernel<<<blocks, 256>>>(news, entf, topf);
    }

    const int m_tiles = (N_NEWS + 127) / 128;  // 782

    // GEMM1: H = tanh(X @ W1 + b1)
    {
        dim3 grid(HIDN / 128, m_tiles);
        gemm_mma_kernel<true, true><<<grid, 256, GEMM_SMEM>>>(
            (const __nv_bfloat16*)p_xh, (const __nv_bfloat16*)p_xl,
            (const __nv_bfloat16*)p_w1h, (const __nv_bfloat16*)p_w1l,
            b1, nullptr, (__nv_bfloat16*)p_hh, (__nv_bfloat16*)p_hl,
            N_NEWS, HIDN, KDIM);
    }
    // GEMM2: out = H @ W2 + b2
    {
        dim3 grid(OUTD / 128, m_tiles);
        gemm_mma_kernel<false, false><<<grid, 256, GEMM_SMEM>>>(
            (const __nv_bfloat16*)p_hh, (const __nv_bfloat16*)p_hl,
            (const __nv_bfloat16*)p_w2h, (const __nv_bfloat16*)p_w2l,
            b2, out, nullptr, nullptr,
            N_NEWS, OUTD, HIDN);
    }
}